// round 6
// baseline (speedup 1.0000x reference)
#include <cuda_runtime.h>
#include <cuda_bf16.h>

// Problem constants (fixed by the dataset)
#define B_TOT   1024
#define S_LEN   2048
#define F_IN    9
#define NOUT    8
#define UDIM    256
#define LBK     3
#define DDIM    11      // NOUT + 3
#define XDIM    33      // LBK * DDIM
#define H1DIM   512     // 2*U
#define T_OUT   2044    // S - 1 - LBK
#define M_ROWS  4
#define NCTA    256     // NCTA * M_ROWS == B_TOT
#define NTHREADS 256

typedef unsigned long long u64;

// Blackwell packed fp32 FMA (2 MACs / instr) — only reachable via PTX fma.rn.f32x2
__device__ __forceinline__ u64 ffma2(u64 a, u64 b, u64 c) {
    u64 d;
    asm("fma.rn.f32x2 %0, %1, %2, %3;" : "=l"(d) : "l"(a), "l"(b), "l"(c));
    return d;
}
__device__ __forceinline__ u64 bcast2(float w) {
    u64 r;
    asm("mov.b64 %0, {%1, %1};" : "=l"(r) : "f"(w));
    return r;
}
__device__ __forceinline__ float2 unpack2(u64 v) {
    float2 f;
    asm("mov.b64 {%0, %1}, %2;" : "=f"(f.x), "=f"(f.y) : "l"(v));
    return f;
}

__global__ __launch_bounds__(NTHREADS, 2)
void dps_kernel(const float* __restrict__ inputs,
                const float* __restrict__ ln1_g, const float* __restrict__ ln1_b,
                const float* __restrict__ w1,    const float* __restrict__ b1,
                const float* __restrict__ w2,    const float* __restrict__ b2,
                const float* __restrict__ wu,    const float* __restrict__ bu,
                const float* __restrict__ ln2_g, const float* __restrict__ ln2_b,
                const float* __restrict__ wbeta,
                const float* __restrict__ wd1,   const float* __restrict__ bd1,
                const float* __restrict__ wd2,   const float* __restrict__ bd2,
                const int*   __restrict__ fix,
                float* __restrict__ out)
{
    // All activation tensors are m-contiguous: [k][M_ROWS] so an aligned 8B
    // shared load yields an (m,m+1) f32x2 pair directly.
    __shared__ __align__(16) float s_x   [XDIM][M_ROWS];
    __shared__ __align__(16) float s_big [H1DIM][M_ROWS];   // h1 (enc) then t1 (dec)
    __shared__ __align__(16) float s_h   [UDIM][M_ROWS];
    __shared__ __align__(16) float s_comb[260][M_ROWS];     // [0..255]=st, [256]=ect
    __shared__ __align__(16) float s_win [LBK][NOUT][M_ROWS];
    __shared__ __align__(16) float s_y   [NOUT][M_ROWS];
    __shared__ float s_red[8][12];                          // per-warp partials
    __shared__ float2 s_stat[M_ROWS];                       // (mean, rstd) for LN2

    const int tid  = threadIdx.x;
    const int lane = tid & 31;
    const int wid  = tid >> 5;
    const int row0 = blockIdx.x * M_ROWS;

    const int fix0 = fix[0];
    const int fix1 = fix[1];

    // ---- init window: win[t][n][m] = inputs[row0+m, t, 1+n]
    for (int idx = tid; idx < LBK * NOUT * M_ROWS; idx += NTHREADS) {
        int m = idx & 3;
        int n = (idx >> 2) & 7;
        int t = idx >> 5;
        s_win[t][n][m] = inputs[((size_t)(row0 + m) * S_LEN + t) * F_IN + 1 + n];
    }
    __syncthreads();

    for (int i = LBK; i < S_LEN - 1; ++i) {
        // ================= Phase A: build x (lc + win), LayerNorm1 =================
        if (tid < M_ROWS * LBK) {
            int m = tid & 3, t = tid >> 2;
            int s = i - LBK + t;
            size_t base = ((size_t)(row0 + m) * S_LEN + s) * F_IN;
            float ld = inputs[base];
            float df = (s > 0) ? (ld - inputs[base - F_IN]) : 0.0f;
            float x[DDIM];
            x[0] = ld; x[1] = ld; x[2] = df;
            #pragma unroll
            for (int n = 0; n < NOUT; ++n) x[3 + n] = s_win[t][n][m];
            float mean = 0.f;
            #pragma unroll
            for (int d = 0; d < DDIM; ++d) mean += x[d];
            mean *= (1.0f / DDIM);
            float var = 0.f;
            #pragma unroll
            for (int d = 0; d < DDIM; ++d) { float c = x[d] - mean; var += c * c; }
            var *= (1.0f / DDIM);
            float rs = rsqrtf(var + 1e-3f);
            #pragma unroll
            for (int d = 0; d < DDIM; ++d)
                s_x[t * DDIM + d][m] = (x[d] - mean) * rs * ln1_g[d] + ln1_b[d];
        }
        __syncthreads();

        // ================= Phase B: enc1 (33 -> 512) + tanh ========================
        {
            u64 a00 = 0, a01 = 0, a10 = 0, a11 = 0;   // {j0,j1} x {m01,m23}
            const int j0 = tid, j1 = tid + 256;
            const u64* xx = (const u64*)&s_x[0][0];
            #pragma unroll 3
            for (int k = 0; k < XDIM; ++k) {
                u64 wa = bcast2(w1[k * H1DIM + j0]);
                u64 wb = bcast2(w1[k * H1DIM + j1]);
                u64 x01 = xx[2 * k], x23 = xx[2 * k + 1];
                a00 = ffma2(x01, wa, a00);  a01 = ffma2(x23, wa, a01);
                a10 = ffma2(x01, wb, a10);  a11 = ffma2(x23, wb, a11);
            }
            float ba = b1[j0], bb = b1[j1];
            float2 p0 = unpack2(a00), p1 = unpack2(a01);
            float2 q0 = unpack2(a10), q1 = unpack2(a11);
            *(float4*)&s_big[j0][0] = make_float4(tanhf(p0.x + ba), tanhf(p0.y + ba),
                                                 tanhf(p1.x + ba), tanhf(p1.y + ba));
            *(float4*)&s_big[j1][0] = make_float4(tanhf(q0.x + bb), tanhf(q0.y + bb),
                                                 tanhf(q1.x + bb), tanhf(q1.y + bb));
        }
        __syncthreads();

        // ================= Phase C: enc2 (512 -> 256) ==============================
        float4 hreg;
        {
            u64 c0 = 0, c1 = 0;
            const int j = tid;
            const u64* hh = (const u64*)&s_big[0][0];
            #pragma unroll 4
            for (int k = 0; k < H1DIM; ++k) {
                u64 wv = bcast2(w2[k * UDIM + j]);
                c0 = ffma2(hh[2 * k], wv, c0);
                c1 = ffma2(hh[2 * k + 1], wv, c1);
            }
            float bb = b2[j];
            float2 p0 = unpack2(c0), p1 = unpack2(c1);
            hreg = make_float4(p0.x + bb, p0.y + bb, p1.x + bb, p1.y + bb);
            *(float4*)&s_h[j][0] = hreg;
        }
        __syncthreads();

        // ================= Phase D: upd (256 -> 256), beta partial, LN2 ============
        float u[M_ROWS];
        {
            u64 c0 = 0, c1 = 0;
            const int j = tid;
            const u64* hh = (const u64*)&s_h[0][0];
            #pragma unroll 4
            for (int k = 0; k < UDIM; ++k) {
                u64 wv = bcast2(wu[k * UDIM + j]);
                c0 = ffma2(hh[2 * k], wv, c0);
                c1 = ffma2(hh[2 * k + 1], wv, c1);
            }
            float bb = bu[j];
            float2 p0 = unpack2(c0), p1 = unpack2(c1);
            u[0] = p0.x + bb; u[1] = p0.y + bb; u[2] = p1.x + bb; u[3] = p1.y + bb;
        }
        {   // block-wide reductions: sum(u), sum(u^2), ect = h . beta  (per m)
            float bw = wbeta[tid];
            float su[M_ROWS], sq[M_ROWS], pe[M_ROWS];
            pe[0] = hreg.x * bw; pe[1] = hreg.y * bw; pe[2] = hreg.z * bw; pe[3] = hreg.w * bw;
            #pragma unroll
            for (int m = 0; m < M_ROWS; ++m) { su[m] = u[m]; sq[m] = u[m] * u[m]; }
            #pragma unroll
            for (int o = 16; o > 0; o >>= 1) {
                #pragma unroll
                for (int m = 0; m < M_ROWS; ++m) {
                    su[m] += __shfl_xor_sync(0xffffffffu, su[m], o);
                    sq[m] += __shfl_xor_sync(0xffffffffu, sq[m], o);
                    pe[m] += __shfl_xor_sync(0xffffffffu, pe[m], o);
                }
            }
            if (lane == 0) {
                #pragma unroll
                for (int m = 0; m < M_ROWS; ++m) {
                    s_red[wid][m]     = su[m];
                    s_red[wid][4 + m] = sq[m];
                    s_red[wid][8 + m] = pe[m];
                }
            }
        }
        __syncthreads();
        if (tid < M_ROWS) {
            int m = tid;
            float su = 0.f, sq = 0.f, pe = 0.f;
            #pragma unroll
            for (int w = 0; w < 8; ++w) {
                su += s_red[w][m]; sq += s_red[w][4 + m]; pe += s_red[w][8 + m];
            }
            float mean = su * (1.0f / UDIM);
            float var  = sq * (1.0f / UDIM) - mean * mean;
            s_stat[m] = make_float2(mean, rsqrtf(var + 1e-3f));
            s_comb[UDIM][m] = pe;               // ect (not layernormed)
        }
        __syncthreads();
        {   // normalize u in registers, write st into s_comb
            float g = ln2_g[tid], b = ln2_b[tid];
            float4 st;
            float2 st0 = s_stat[0], st1 = s_stat[1], st2 = s_stat[2], st3 = s_stat[3];
            st.x = (u[0] - st0.x) * st0.y * g + b;
            st.y = (u[1] - st1.x) * st1.y * g + b;
            st.z = (u[2] - st2.x) * st2.y * g + b;
            st.w = (u[3] - st3.x) * st3.y * g + b;
            *(float4*)&s_comb[tid][0] = st;
        }
        __syncthreads();

        // ================= Phase F: dec1 (257 -> 512) + tanh =======================
        {
            u64 a00 = 0, a01 = 0, a10 = 0, a11 = 0;
            const int j0 = tid, j1 = tid + 256;
            const u64* cc = (const u64*)&s_comb[0][0];
            #pragma unroll 4
            for (int k = 0; k < UDIM + 1; ++k) {
                u64 wa = bcast2(wd1[k * H1DIM + j0]);
                u64 wb = bcast2(wd1[k * H1DIM + j1]);
                u64 x01 = cc[2 * k], x23 = cc[2 * k + 1];
                a00 = ffma2(x01, wa, a00);  a01 = ffma2(x23, wa, a01);
                a10 = ffma2(x01, wb, a10);  a11 = ffma2(x23, wb, a11);
            }
            float ba = bd1[j0], bb = bd1[j1];
            float2 p0 = unpack2(a00), p1 = unpack2(a01);
            float2 q0 = unpack2(a10), q1 = unpack2(a11);
            *(float4*)&s_big[j0][0] = make_float4(tanhf(p0.x + ba), tanhf(p0.y + ba),
                                                 tanhf(p1.x + ba), tanhf(p1.y + ba));
            *(float4*)&s_big[j1][0] = make_float4(tanhf(q0.x + bb), tanhf(q0.y + bb),
                                                 tanhf(q1.x + bb), tanhf(q1.y + bb));
        }
        __syncthreads();

        // ================= Phase G: dec2 (512 -> 8), fix override, output ==========
        if (wid < M_ROWS) {
            int m = wid;
            int n = lane & 7;
            int c = lane >> 3;            // 4 chunks of 128
            float acc = 0.f;
            int k0 = c * 128;
            #pragma unroll 4
            for (int k = k0; k < k0 + 128; ++k)
                acc = fmaf(s_big[k][m], wd2[k * NOUT + n], acc);
            acc += __shfl_down_sync(0xffffffffu, acc, 16);
            acc += __shfl_down_sync(0xffffffffu, acc, 8);
            if (lane < 8) {
                float y = acc + bd2[n];
                int b = row0 + m;
                size_t ib = ((size_t)b * S_LEN + (i + 1)) * F_IN;
                if (n == fix0) y = inputs[ib + 1 + fix0];
                if (n == fix1) y = inputs[ib + 1 + fix1];
                s_y[n][m] = y;
                // out shape (NOUT, B, T): out[n, b, t]
                out[(size_t)n * ((size_t)B_TOT * T_OUT) + (size_t)b * T_OUT + (i - LBK)] = y;
            }
        }
        __syncthreads();

        // ---- window shift (each thread owns one (m, n): read-then-write safe)
        if (tid < M_ROWS * NOUT) {
            int m = tid >> 3, n = tid & 7;
            float a = s_win[1][n][m];
            float b = s_win[2][n][m];
            s_win[0][n][m] = a;
            s_win[1][n][m] = b;
            s_win[2][n][m] = s_y[n][m];
        }
        __syncthreads();
    }
}

extern "C" void kernel_launch(void* const* d_in, const int* in_sizes, int n_in,
                              void* d_out, int out_size) {
    const float* inputs = (const float*)d_in[0];
    const float* ln1_g  = (const float*)d_in[1];
    const float* ln1_b  = (const float*)d_in[2];
    const float* w1     = (const float*)d_in[3];
    const float* b1     = (const float*)d_in[4];
    const float* w2     = (const float*)d_in[5];
    const float* b2     = (const float*)d_in[6];
    const float* wu     = (const float*)d_in[7];
    const float* bu     = (const float*)d_in[8];
    const float* ln2_g  = (const float*)d_in[9];
    const float* ln2_b  = (const float*)d_in[10];
    const float* wbeta  = (const float*)d_in[11];
    const float* wd1    = (const float*)d_in[12];
    const float* bd1    = (const float*)d_in[13];
    const float* wd2    = (const float*)d_in[14];
    const float* bd2    = (const float*)d_in[15];
    const int*   fix    = (const int*)  d_in[16];
    float* out = (float*)d_out;

    dps_kernel<<<NCTA, NTHREADS>>>(inputs, ln1_g, ln1_b, w1, b1, w2, b2,
                                   wu, bu, ln2_g, ln2_b, wbeta,
                                   wd1, bd1, wd2, bd2, fix, out);
}

// round 10
// speedup vs baseline: 1.6682x; 1.6682x over previous
#include <cuda_runtime.h>
#include <cuda_bf16.h>

// Problem constants (fixed by the dataset)
#define B_TOT   1024
#define S_LEN   2048
#define F_IN    9
#define NOUT    8
#define UDIM    256
#define LBK     3
#define DDIM    11      // NOUT + 3
#define XDIM    33      // LBK * DDIM
#define H1DIM   512     // 2*U
#define T_OUT   2044    // S - 1 - LBK
#define M_ROWS  8
#define NCTA    128     // NCTA * M_ROWS == B_TOT
#define NTHREADS 512    // 16 warps: B/F one j per thread; C/D k-split halves

__device__ __forceinline__ float tanh_fast(float x) {
    float y;
    asm("tanh.approx.f32 %0, %1;" : "=f"(y) : "f"(x));
    return y;
}

__global__ __launch_bounds__(NTHREADS, 1)
void dps_kernel(const float* __restrict__ inputs,
                const float* __restrict__ ln1_g, const float* __restrict__ ln1_b,
                const float* __restrict__ w1,    const float* __restrict__ b1,
                const float* __restrict__ w2,    const float* __restrict__ b2,
                const float* __restrict__ wu,    const float* __restrict__ bu,
                const float* __restrict__ ln2_g, const float* __restrict__ ln2_b,
                const float* __restrict__ wbeta,
                const float* __restrict__ wd1,   const float* __restrict__ bd1,
                const float* __restrict__ wd2,   const float* __restrict__ bd2,
                const int*   __restrict__ fix,
                float* __restrict__ out)
{
    __shared__ __align__(16) float s_xx [M_ROWS][36];      // post-LN1 x (padded: 36*4=144B, 16B-aligned rows)
    __shared__ __align__(16) float s_big[M_ROWS][H1DIM];   // h1 (enc) then t1 (dec) - aliased
    __shared__ __align__(16) float s_h  [M_ROWS][UDIM];    // encoder output
    __shared__ __align__(16) float s_comb[M_ROWS][260];    // [0..255]=st (after LN2), [256]=ect
    __shared__ __align__(16) float s_part[UDIM][M_ROWS];   // k-split partial accumulators
    __shared__ float s_win[M_ROWS][LBK][NOUT];
    __shared__ float s_y  [M_ROWS][NOUT];

    const int tid  = threadIdx.x;
    const int lane = tid & 31;
    const int wid  = tid >> 5;
    const int row0 = blockIdx.x * M_ROWS;

    const int fix0 = fix[0];
    const int fix1 = fix[1];

    // ---- init window: win[m][t][n] = inputs[row0+m, t, 1+n]
    for (int idx = tid; idx < M_ROWS * LBK * NOUT; idx += NTHREADS) {
        int m = idx / (LBK * NOUT);
        int r = idx % (LBK * NOUT);
        int t = r / NOUT, n = r % NOUT;
        s_win[m][t][n] = inputs[((size_t)(row0 + m) * S_LEN + t) * F_IN + 1 + n];
    }
    __syncthreads();

    for (int i = LBK; i < S_LEN - 1; ++i) {
        // ================= Phase A: build x (lc + win), LayerNorm1 =================
        if (tid < M_ROWS * LBK) {
            int m = tid / LBK, t = tid % LBK;
            int s = i - LBK + t;
            size_t base = ((size_t)(row0 + m) * S_LEN + s) * F_IN;
            float ld = inputs[base];
            float df = (s > 0) ? (ld - inputs[base - F_IN]) : 0.0f;
            float x[DDIM];
            x[0] = ld; x[1] = ld; x[2] = df;
            #pragma unroll
            for (int n = 0; n < NOUT; ++n) x[3 + n] = s_win[m][t][n];
            float mean = 0.f;
            #pragma unroll
            for (int d = 0; d < DDIM; ++d) mean += x[d];
            mean *= (1.0f / DDIM);
            float var = 0.f;
            #pragma unroll
            for (int d = 0; d < DDIM; ++d) { float c = x[d] - mean; var += c * c; }
            var *= (1.0f / DDIM);
            float rs = rsqrtf(var + 1e-3f);
            #pragma unroll
            for (int d = 0; d < DDIM; ++d)
                s_xx[m][t * DDIM + d] = (x[d] - mean) * rs * ln1_g[d] + ln1_b[d];
        }
        __syncthreads();

        // ================= Phase B: enc1 (33 -> 512) + tanh, one j per thread ======
        {
            float acc[M_ROWS];
            #pragma unroll
            for (int m = 0; m < M_ROWS; ++m) acc[m] = 0.f;
            const int j = tid;
            #pragma unroll 4
            for (int kk = 0; kk < 32; kk += 4) {
                float wv0 = w1[(kk + 0) * H1DIM + j];
                float wv1 = w1[(kk + 1) * H1DIM + j];
                float wv2 = w1[(kk + 2) * H1DIM + j];
                float wv3 = w1[(kk + 3) * H1DIM + j];
                #pragma unroll
                for (int m = 0; m < M_ROWS; ++m) {
                    float4 xv = *reinterpret_cast<const float4*>(&s_xx[m][kk]);
                    acc[m] = fmaf(xv.x, wv0, acc[m]);
                    acc[m] = fmaf(xv.y, wv1, acc[m]);
                    acc[m] = fmaf(xv.z, wv2, acc[m]);
                    acc[m] = fmaf(xv.w, wv3, acc[m]);
                }
            }
            {   // tail k = 32
                float wv = w1[32 * H1DIM + j];
                #pragma unroll
                for (int m = 0; m < M_ROWS; ++m)
                    acc[m] = fmaf(s_xx[m][32], wv, acc[m]);
            }
            float bb = b1[j];
            #pragma unroll
            for (int m = 0; m < M_ROWS; ++m)
                s_big[m][j] = tanh_fast(acc[m] + bb);
        }
        __syncthreads();

        // ================= Phase C: enc2 (512 -> 256), k-split across thread halves =
        {
            const int j = tid & 255;
            const int h = tid >> 8;            // 0: k in [0,256), 1: k in [256,512)
            const int k0 = h << 8;
            float acc[M_ROWS];
            #pragma unroll
            for (int m = 0; m < M_ROWS; ++m) acc[m] = 0.f;
            #pragma unroll 4
            for (int kk = k0; kk < k0 + 256; kk += 4) {
                float wv0 = w2[(kk + 0) * UDIM + j];
                float wv1 = w2[(kk + 1) * UDIM + j];
                float wv2 = w2[(kk + 2) * UDIM + j];
                float wv3 = w2[(kk + 3) * UDIM + j];
                #pragma unroll
                for (int m = 0; m < M_ROWS; ++m) {
                    float4 hv = *reinterpret_cast<const float4*>(&s_big[m][kk]);
                    acc[m] = fmaf(hv.x, wv0, acc[m]);
                    acc[m] = fmaf(hv.y, wv1, acc[m]);
                    acc[m] = fmaf(hv.z, wv2, acc[m]);
                    acc[m] = fmaf(hv.w, wv3, acc[m]);
                }
            }
            if (h == 1) {
                *reinterpret_cast<float4*>(&s_part[j][0]) =
                    make_float4(acc[0], acc[1], acc[2], acc[3]);
                *reinterpret_cast<float4*>(&s_part[j][4]) =
                    make_float4(acc[4], acc[5], acc[6], acc[7]);
            }
            __syncthreads();
            if (h == 0) {
                float bb = b2[j];
                float4 p0 = *reinterpret_cast<const float4*>(&s_part[j][0]);
                float4 p1 = *reinterpret_cast<const float4*>(&s_part[j][4]);
                s_h[0][j] = acc[0] + p0.x + bb;
                s_h[1][j] = acc[1] + p0.y + bb;
                s_h[2][j] = acc[2] + p0.z + bb;
                s_h[3][j] = acc[3] + p0.w + bb;
                s_h[4][j] = acc[4] + p1.x + bb;
                s_h[5][j] = acc[5] + p1.y + bb;
                s_h[6][j] = acc[6] + p1.z + bb;
                s_h[7][j] = acc[7] + p1.w + bb;
            }
        }
        __syncthreads();

        // ================= Phase D: upd (256 -> 256) k-split + beta reduction ======
        {   // ect[m] = h[m] . beta_w   (warps 0..7, one per row; reads s_h - ready)
            if (wid < M_ROWS) {
                int m = wid;
                float p = 0.f;
                for (int k = lane; k < UDIM; k += 32) p = fmaf(s_h[m][k], wbeta[k], p);
                #pragma unroll
                for (int o = 16; o > 0; o >>= 1) p += __shfl_xor_sync(0xffffffffu, p, o);
                if (lane == 0) s_comb[m][UDIM] = p;
            }
        }
        {
            const int j = tid & 255;
            const int h = tid >> 8;            // 0: k in [0,128), 1: k in [128,256)
            const int k0 = h << 7;
            float acc[M_ROWS];
            #pragma unroll
            for (int m = 0; m < M_ROWS; ++m) acc[m] = 0.f;
            #pragma unroll 4
            for (int kk = k0; kk < k0 + 128; kk += 4) {
                float wv0 = wu[(kk + 0) * UDIM + j];
                float wv1 = wu[(kk + 1) * UDIM + j];
                float wv2 = wu[(kk + 2) * UDIM + j];
                float wv3 = wu[(kk + 3) * UDIM + j];
                #pragma unroll
                for (int m = 0; m < M_ROWS; ++m) {
                    float4 hv = *reinterpret_cast<const float4*>(&s_h[m][kk]);
                    acc[m] = fmaf(hv.x, wv0, acc[m]);
                    acc[m] = fmaf(hv.y, wv1, acc[m]);
                    acc[m] = fmaf(hv.z, wv2, acc[m]);
                    acc[m] = fmaf(hv.w, wv3, acc[m]);
                }
            }
            if (h == 1) {
                *reinterpret_cast<float4*>(&s_part[j][0]) =
                    make_float4(acc[0], acc[1], acc[2], acc[3]);
                *reinterpret_cast<float4*>(&s_part[j][4]) =
                    make_float4(acc[4], acc[5], acc[6], acc[7]);
            }
            __syncthreads();
            if (h == 0) {
                float bb = bu[j];
                float4 p0 = *reinterpret_cast<const float4*>(&s_part[j][0]);
                float4 p1 = *reinterpret_cast<const float4*>(&s_part[j][4]);
                s_comb[0][j] = acc[0] + p0.x + bb;
                s_comb[1][j] = acc[1] + p0.y + bb;
                s_comb[2][j] = acc[2] + p0.z + bb;
                s_comb[3][j] = acc[3] + p0.w + bb;
                s_comb[4][j] = acc[4] + p1.x + bb;
                s_comb[5][j] = acc[5] + p1.y + bb;
                s_comb[6][j] = acc[6] + p1.z + bb;
                s_comb[7][j] = acc[7] + p1.w + bb;
            }
        }
        __syncthreads();

        // ================= Phase E: LayerNorm2 over 256 (warps 0..7, one per row) ==
        if (wid < M_ROWS) {
            int m = wid;
            float v[8];
            float4 a = *reinterpret_cast<const float4*>(&s_comb[m][lane * 8]);
            float4 b = *reinterpret_cast<const float4*>(&s_comb[m][lane * 8 + 4]);
            v[0]=a.x; v[1]=a.y; v[2]=a.z; v[3]=a.w;
            v[4]=b.x; v[5]=b.y; v[6]=b.z; v[7]=b.w;
            float sum = 0.f, sq = 0.f;
            #pragma unroll
            for (int q = 0; q < 8; ++q) { sum += v[q]; sq = fmaf(v[q], v[q], sq); }
            #pragma unroll
            for (int o = 16; o > 0; o >>= 1) {
                sum += __shfl_xor_sync(0xffffffffu, sum, o);
                sq  += __shfl_xor_sync(0xffffffffu, sq, o);
            }
            float mean = sum * (1.0f / UDIM);
            float var  = sq * (1.0f / UDIM) - mean * mean;
            float rs = rsqrtf(var + 1e-3f);
            #pragma unroll
            for (int q = 0; q < 8; ++q) {
                int k = lane * 8 + q;
                s_comb[m][k] = (v[q] - mean) * rs * ln2_g[k] + ln2_b[k];
            }
        }
        __syncthreads();

        // ================= Phase F: dec1 (257 -> 512) + tanh, one j per thread =====
        {
            float acc[M_ROWS];
            #pragma unroll
            for (int m = 0; m < M_ROWS; ++m) acc[m] = 0.f;
            const int j = tid;
            #pragma unroll 4
            for (int kk = 0; kk < 256; kk += 4) {
                float wv0 = wd1[(kk + 0) * H1DIM + j];
                float wv1 = wd1[(kk + 1) * H1DIM + j];
                float wv2 = wd1[(kk + 2) * H1DIM + j];
                float wv3 = wd1[(kk + 3) * H1DIM + j];
                #pragma unroll
                for (int m = 0; m < M_ROWS; ++m) {
                    float4 cv = *reinterpret_cast<const float4*>(&s_comb[m][kk]);
                    acc[m] = fmaf(cv.x, wv0, acc[m]);
                    acc[m] = fmaf(cv.y, wv1, acc[m]);
                    acc[m] = fmaf(cv.z, wv2, acc[m]);
                    acc[m] = fmaf(cv.w, wv3, acc[m]);
                }
            }
            {   // tail k = 256 (ect)
                float wv = wd1[256 * H1DIM + j];
                #pragma unroll
                for (int m = 0; m < M_ROWS; ++m)
                    acc[m] = fmaf(s_comb[m][UDIM], wv, acc[m]);
            }
            float bb = bd1[j];
            #pragma unroll
            for (int m = 0; m < M_ROWS; ++m)
                s_big[m][j] = tanh_fast(acc[m] + bb);
        }
        __syncthreads();

        // ================= Phase G: dec2 (512 -> 8), fix override, output ==========
        if (wid < M_ROWS) {
            int m = wid;
            int n = lane & 7;
            int c = lane >> 3;            // 4 chunks of 128
            float acc = 0.f;
            int k0 = c * 128;
            #pragma unroll 4
            for (int k = k0; k < k0 + 128; ++k)
                acc = fmaf(s_big[m][k], wd2[k * NOUT + n], acc);
            acc += __shfl_down_sync(0xffffffffu, acc, 16);
            acc += __shfl_down_sync(0xffffffffu, acc, 8);
            if (lane < 8) {
                float y = acc + bd2[n];
                int b = row0 + m;
                size_t ib = ((size_t)b * S_LEN + (i + 1)) * F_IN;
                if (n == fix0) y = inputs[ib + 1 + fix0];
                if (n == fix1) y = inputs[ib + 1 + fix1];
                s_y[m][n] = y;
                // out shape (NOUT, B, T): out[n, b, t]
                out[(size_t)n * ((size_t)B_TOT * T_OUT) + (size_t)b * T_OUT + (i - LBK)] = y;
            }
        }
        __syncthreads();

        // ---- window shift (each thread owns one (m, n): read-then-write safe)
        if (tid < M_ROWS * NOUT) {
            int m = tid >> 3, n = tid & 7;
            float a = s_win[m][1][n];
            float b = s_win[m][2][n];
            s_win[m][0][n] = a;
            s_win[m][1][n] = b;
            s_win[m][2][n] = s_y[m][n];
        }
        __syncthreads();
    }
}

extern "C" void kernel_launch(void* const* d_in, const int* in_sizes, int n_in,
                              void* d_out, int out_size) {
    const float* inputs = (const float*)d_in[0];
    const float* ln1_g  = (const float*)d_in[1];
    const float* ln1_b  = (const float*)d_in[2];
    const float* w1     = (const float*)d_in[3];
    const float* b1     = (const float*)d_in[4];
    const float* w2     = (const float*)d_in[5];
    const float* b2     = (const float*)d_in[6];
    const float* wu     = (const float*)d_in[7];
    const float* bu     = (const float*)d_in[8];
    const float* ln2_g  = (const float*)d_in[9];
    const float* ln2_b  = (const float*)d_in[10];
    const float* wbeta  = (const float*)d_in[11];
    const float* wd1    = (const float*)d_in[12];
    const float* bd1    = (const float*)d_in[13];
    const float* wd2    = (const float*)d_in[14];
    const float* bd2    = (const float*)d_in[15];
    const int*   fix    = (const int*)  d_in[16];
    float* out = (float*)d_out;

    dps_kernel<<<NCTA, NTHREADS>>>(inputs, ln1_g, ln1_b, w1, b1, w2, b2,
                                   wu, bu, ln2_g, ln2_b, wbeta,
                                   wd1, bd1, wd2, bd2, fix, out);
}